// round 1
// baseline (speedup 1.0000x reference)
#include <cuda_runtime.h>
#include <cuda_bf16.h>
#include <cstdint>

// Problem constants (fixed by the reference):
//   a    [B,H,M,K] fp32
//   mask [B,1,M,K] int32 (0/1)
//   b    [B,H,K,N] fp32
//   out  [B,H,M,N] fp32 = (a*mask) @ b  batched over (B,H)
static constexpr int Bc = 2;
static constexpr int Hc = 16;
static constexpr int Mc = 2048;
static constexpr int Kc = 2048;
static constexpr int Nc = 256;

static constexpr int BM = 128;
static constexpr int BN = 128;
static constexpr int BK = 8;
static constexpr int NTHREADS = 256;

__global__ __launch_bounds__(NTHREADS, 2)
void masked_gemm_kernel(const float* __restrict__ A,
                        const int*   __restrict__ Mask,
                        const float* __restrict__ Bm,
                        float*       __restrict__ C)
{
    __shared__ float As[BK][BM];   // transposed A tile: As[k][m]
    __shared__ float Bs[BK][BN];   // B tile: Bs[k][n]

    const int bh = blockIdx.z;           // 0..31  (b*H + h)
    const int bb = bh / Hc;              // batch index for mask

    const float* a    = A    + (size_t)bh * Mc * Kc;
    const int*   mk   = Mask + (size_t)bb * Mc * Kc;
    const float* bmat = Bm   + (size_t)bh * Kc * Nc;
    float*       c    = C    + (size_t)bh * Mc * Nc;

    const int tid = threadIdx.x;
    const int tx  = tid & 15;            // 0..15 -> N
    const int ty  = tid >> 4;            // 0..15 -> M

    const int rowBase = blockIdx.y * BM;
    const int colBase = blockIdx.x * BN;

    // Global load mapping (one float4 per thread per tile):
    // A tile: 128 rows x 8 cols -> thread loads (row = tid>>1, col4 = (tid&1)*4)
    const int arow = tid >> 1;
    const int acol = (tid & 1) * 4;
    // B tile: 8 rows x 128 cols -> thread loads (row = tid>>5, col4 = (tid&31)*4)
    const int brow = tid >> 5;
    const int bcol = (tid & 31) * 4;

    const float* aPtr = a  + (size_t)(rowBase + arow) * Kc + acol;
    const int*   mPtr = mk + (size_t)(rowBase + arow) * Kc + acol;
    const float* bPtr = bmat + (size_t)brow * Nc + colBase + bcol;

    float acc[8][8];
    #pragma unroll
    for (int i = 0; i < 8; i++)
        #pragma unroll
        for (int j = 0; j < 8; j++)
            acc[i][j] = 0.0f;

    for (int k0 = 0; k0 < Kc; k0 += BK) {
        // ---- fill A tile (mask fused) ----
        float4 av = *(const float4*)(aPtr + k0);
        int4   mv = *(const int4*)(mPtr + k0);
        As[acol + 0][arow] = av.x * (float)mv.x;
        As[acol + 1][arow] = av.y * (float)mv.y;
        As[acol + 2][arow] = av.z * (float)mv.z;
        As[acol + 3][arow] = av.w * (float)mv.w;

        // ---- fill B tile ----
        *(float4*)&Bs[brow][bcol] = *(const float4*)(bPtr + (size_t)k0 * Nc);

        __syncthreads();

        #pragma unroll
        for (int kk = 0; kk < BK; kk++) {
            float ra[8], rb[8];
            *(float4*)(ra)     = *(const float4*)&As[kk][ty * 4];
            *(float4*)(ra + 4) = *(const float4*)&As[kk][64 + ty * 4];
            *(float4*)(rb)     = *(const float4*)&Bs[kk][tx * 4];
            *(float4*)(rb + 4) = *(const float4*)&Bs[kk][64 + tx * 4];
            #pragma unroll
            for (int i = 0; i < 8; i++)
                #pragma unroll
                for (int j = 0; j < 8; j++)
                    acc[i][j] += ra[i] * rb[j];
        }

        __syncthreads();
    }

    // ---- epilogue: two 4-wide column segments per row ----
    #pragma unroll
    for (int i = 0; i < 8; i++) {
        const int m = rowBase + ((i < 4) ? (ty * 4 + i) : (64 + ty * 4 + i - 4));
        float4 v0 = make_float4(acc[i][0], acc[i][1], acc[i][2], acc[i][3]);
        float4 v1 = make_float4(acc[i][4], acc[i][5], acc[i][6], acc[i][7]);
        *(float4*)(c + (size_t)m * Nc + colBase + tx * 4)      = v0;
        *(float4*)(c + (size_t)m * Nc + colBase + 64 + tx * 4) = v1;
    }
}

extern "C" void kernel_launch(void* const* d_in, const int* in_sizes, int n_in,
                              void* d_out, int out_size)
{
    const float* a    = (const float*)d_in[0];   // [B,H,M,K] fp32
    const int*   mask = (const int*)d_in[1];     // [B,1,M,K] int32
    const float* b    = (const float*)d_in[2];   // [B,H,K,N] fp32
    float*       out  = (float*)d_out;           // [B,H,M,N] fp32

    dim3 grid(Nc / BN, Mc / BM, Bc * Hc);        // (2, 16, 32)
    dim3 block(NTHREADS);
    masked_gemm_kernel<<<grid, block>>>(a, mask, b, out);
}

// round 5
// speedup vs baseline: 1.9088x; 1.9088x over previous
#include <cuda_runtime.h>
#include <cuda_fp16.h>
#include <cstdint>

// ── Problem constants ───────────────────────────────────────────────
static constexpr int Bc = 2, Hc = 16, Mc = 2048, Kc = 2048, Nc = 256;

// ── Tile config ─────────────────────────────────────────────────────
static constexpr int BM = 128;           // CTA M tile
static constexpr int BN = 256;           // CTA N tile (full N)
static constexpr int BK = 32;            // K per outer iter
static constexpr int NTH = 512;          // 16 warps
static constexpr int OUTER = Kc / BK;    // 64

// fp16 tile rows padded to 80B (32 fp16 = 64B data + 16B pad) -> conflict-free LDSM
static constexpr int ROWB = 80;

// ── SMEM layout (dynamic, bytes) ────────────────────────────────────
static constexpr int SM_SA = 0;                       // A fp32 staging  2 x 16384
static constexpr int SM_SM = 32768;                   // mask staging    2 x 16384
static constexpr int SM_SB = 65536;                   // B fp32 staging  2 x 32768
static constexpr int SM_AH = 131072;                  // A hi fp16 tile 128*80
static constexpr int SM_AL = SM_AH + BM * ROWB;       // A lo
static constexpr int SM_BH = SM_AL + BM * ROWB;       // B hi fp16 tile 256*80
static constexpr int SM_BL = SM_BH + BN * ROWB;       // B lo
static constexpr int SMEM_BYTES = SM_BL + BN * ROWB;  // 192512 (~188KB)

// ── asm helpers ─────────────────────────────────────────────────────
__device__ __forceinline__ uint32_t smem_u32(const void* p) {
    uint32_t a;
    asm("{ .reg .u64 t; cvta.to.shared.u64 t, %1; cvt.u32.u64 %0, t; }" : "=r"(a) : "l"(p));
    return a;
}

#define CP16(dst, src) \
    asm volatile("cp.async.cg.shared.global [%0], [%1], 16;" :: "r"(dst), "l"(src))
#define CP_COMMIT() asm volatile("cp.async.commit_group;" ::: "memory")
#define CP_WAIT1()  asm volatile("cp.async.wait_group 1;" ::: "memory")

#define LDSM4(r, addr) \
    asm volatile("ldmatrix.sync.aligned.m8n8.x4.shared.b16 {%0,%1,%2,%3}, [%4];" \
        : "=r"((r)[0]), "=r"((r)[1]), "=r"((r)[2]), "=r"((r)[3]) : "r"(addr))

#define MMA16816(d, a, b0, b1) \
    asm volatile("mma.sync.aligned.m16n8k16.row.col.f32.f16.f16.f32 " \
        "{%0,%1,%2,%3}, {%4,%5,%6,%7}, {%8,%9}, {%0,%1,%2,%3};" \
        : "+f"((d)[0]), "+f"((d)[1]), "+f"((d)[2]), "+f"((d)[3]) \
        : "r"((a)[0]), "r"((a)[1]), "r"((a)[2]), "r"((a)[3]), "r"(b0), "r"(b1))

// split two fp32 into packed fp16x2 hi + fp16x2 lo (lo = residual)
__device__ __forceinline__ void splitp(float v0, float v1, uint32_t& h, uint32_t& l) {
    __half h0 = __float2half_rn(v0), h1 = __float2half_rn(v1);
    float  r0 = v0 - __half2float(h0), r1 = v1 - __half2float(h1);
    __half l0 = __float2half_rn(r0), l1 = __float2half_rn(r1);
    h = ((uint32_t)__half_as_ushort(h1) << 16) | __half_as_ushort(h0);
    l = ((uint32_t)__half_as_ushort(l1) << 16) | __half_as_ushort(l0);
}

// ── Kernel ──────────────────────────────────────────────────────────
__global__ __launch_bounds__(NTH, 1)
void masked_gemm_hmma(const float* __restrict__ A,
                      const int*   __restrict__ Mask,
                      const float* __restrict__ Bm,
                      float*       __restrict__ C)
{
    extern __shared__ char smem[];
    const uint32_t sb = smem_u32(smem);

    const int tid  = threadIdx.x;
    const int wid  = tid >> 5;
    const int lane = tid & 31;

    const int mtile = blockIdx.x;        // 0..15
    const int bh    = blockIdx.y;        // 0..31
    const int bb    = bh >> 4;
    const int rowBase = mtile * BM;

    const float* Ag = A    + (size_t)bh * Mc * Kc;
    const int*   Mg = Mask + (size_t)bb * Mc * Kc;
    const float* Bg = Bm   + (size_t)bh * Kc * Nc;
    float*       Cg = C    + (size_t)bh * Mc * Nc;

    // ---- cp.async stage issue for iter 'it' into buffer p ----
    auto issue_stage = [&](int it, int p) {
        const int k0 = it * BK;
        #pragma unroll
        for (int i = 0; i < 2; ++i) {                 // A + mask: 1024 16B chunks each
            int idx = i * NTH + tid;
            int m = idx >> 3, c = idx & 7;
            const float* ga = Ag + (size_t)(rowBase + m) * Kc + k0 + c * 4;
            const int*   gm = Mg + (size_t)(rowBase + m) * Kc + k0 + c * 4;
            CP16(sb + SM_SA + p * 16384 + m * 128 + c * 16, ga);
            CP16(sb + SM_SM + p * 16384 + m * 128 + c * 16, gm);
        }
        #pragma unroll
        for (int i = 0; i < 4; ++i) {                 // B: 2048 16B chunks
            int idx = i * NTH + tid;
            int k = idx >> 6, c = idx & 63;
            const float* gb = Bg + (size_t)(k0 + k) * Nc + c * 4;
            CP16(sb + SM_SB + p * 32768 + k * 1024 + c * 16, gb);
        }
    };

    // ---- warp MMA coordinates ----
    const int wm = wid >> 2;             // 0..3 -> M offset 32*wm
    const int wn = wid & 3;              // 0..3 -> N offset 64*wn
    const uint32_t lrow = lane & 15;
    const uint32_t lcb  = lane >> 4;
    const uint32_t aoff = (uint32_t)((wm * 32 + lrow) * ROWB + lcb * 16);
    const uint32_t boff = (uint32_t)((wn * 64 + lrow) * ROWB + lcb * 16);

    float acc[2][4][2][4];               // [mt][j][n8half][4]
    #pragma unroll
    for (int a0 = 0; a0 < 2; ++a0)
        #pragma unroll
        for (int a1 = 0; a1 < 4; ++a1)
            #pragma unroll
            for (int a2 = 0; a2 < 2; ++a2)
                #pragma unroll
                for (int a3 = 0; a3 < 4; ++a3) acc[a0][a1][a2][a3] = 0.0f;

    // prologue
    issue_stage(0, 0);
    CP_COMMIT();

    int p = 0;
    #pragma unroll 1
    for (int it = 0; it < OUTER; ++it) {
        if (it + 1 < OUTER) issue_stage(it + 1, p ^ 1);
        CP_COMMIT();
        CP_WAIT1();                       // stage[p] complete (1 group may remain in flight)
        __syncthreads();                  // staging visible to all; prev MMA done -> tiles reusable

        // ---- convert A (mask fused) ----
        {
            const int m = tid >> 2, kb = tid & 3;
            const char* srcA = smem + SM_SA + p * 16384 + m * 128 + kb * 32;
            const char* srcM = smem + SM_SM + p * 16384 + m * 128 + kb * 32;
            float4 a0 = *(const float4*)(srcA);
            float4 a1 = *(const float4*)(srcA + 16);
            int4   m0 = *(const int4*)(srcM);
            int4   m1 = *(const int4*)(srcM + 16);
            float v[8] = { m0.x ? a0.x : 0.0f, m0.y ? a0.y : 0.0f,
                           m0.z ? a0.z : 0.0f, m0.w ? a0.w : 0.0f,
                           m1.x ? a1.x : 0.0f, m1.y ? a1.y : 0.0f,
                           m1.z ? a1.z : 0.0f, m1.w ? a1.w : 0.0f };
            uint4 hv, lv;
            splitp(v[0], v[1], hv.x, lv.x);
            splitp(v[2], v[3], hv.y, lv.y);
            splitp(v[4], v[5], hv.z, lv.z);
            splitp(v[6], v[7], hv.w, lv.w);
            *(uint4*)(smem + SM_AH + m * ROWB + kb * 16) = hv;
            *(uint4*)(smem + SM_AL + m * ROWB + kb * 16) = lv;
        }
        // ---- convert B (transpose to [n][k]) ----
        {
            const int n = tid & 255, kh = tid >> 8;   // kh in {0,1}: k 0-15 / 16-31
            const char* srcB = smem + SM_SB + p * 32768 + n * 4 + kh * 16 * 1024;
            float v[16];
            #pragma unroll
            for (int j = 0; j < 16; ++j)
                v[j] = *(const float*)(srcB + j * 1024);
            uint4 h0, h1, l0, l1;
            splitp(v[0],  v[1],  h0.x, l0.x);  splitp(v[2],  v[3],  h0.y, l0.y);
            splitp(v[4],  v[5],  h0.z, l0.z);  splitp(v[6],  v[7],  h0.w, l0.w);
            splitp(v[8],  v[9],  h1.x, l1.x);  splitp(v[10], v[11], h1.y, l1.y);
            splitp(v[12], v[13], h1.z, l1.z);  splitp(v[14], v[15], h1.w, l1.w);
            char* dH = smem + SM_BH + n * ROWB + kh * 32;
            char* dL = smem + SM_BL + n * ROWB + kh * 32;
            *(uint4*)(dH)      = h0;  *(uint4*)(dH + 16) = h1;
            *(uint4*)(dL)      = l0;  *(uint4*)(dL + 16) = l1;
        }

        __syncthreads();                  // fp16 tiles visible

        // ---- MMA: 2 k16 steps x (2 mt x 8 n8 x 3 products) ----
        #pragma unroll
        for (int s = 0; s < 2; ++s) {
            uint32_t ah[2][4], al[2][4];
            LDSM4(ah[0], sb + SM_AH + aoff + s * 32);
            LDSM4(ah[1], sb + SM_AH + aoff + s * 32 + 16 * ROWB);
            LDSM4(al[0], sb + SM_AL + aoff + s * 32);
            LDSM4(al[1], sb + SM_AL + aoff + s * 32 + 16 * ROWB);
            #pragma unroll
            for (int j = 0; j < 4; ++j) {
                uint32_t bh4[4], bl4[4];
                LDSM4(bh4, sb + SM_BH + boff + j * 16 * ROWB + s * 32);
                LDSM4(bl4, sb + SM_BL + boff + j * 16 * ROWB + s * 32);
                #pragma unroll
                for (int mt = 0; mt < 2; ++mt) {
                    MMA16816(acc[mt][j][0], ah[mt], bh4[0], bh4[2]);
                    MMA16816(acc[mt][j][0], ah[mt], bl4[0], bl4[2]);
                    MMA16816(acc[mt][j][0], al[mt], bh4[0], bh4[2]);
                    MMA16816(acc[mt][j][1], ah[mt], bh4[1], bh4[3]);
                    MMA16816(acc[mt][j][1], ah[mt], bl4[1], bl4[3]);
                    MMA16816(acc[mt][j][1], al[mt], bh4[1], bh4[3]);
                }
            }
        }
        p ^= 1;
    }

    // ---- epilogue: write accumulators ----
    const int r     = lane >> 2;
    const int cpair = (lane & 3) * 2;
    #pragma unroll
    for (int mt = 0; mt < 2; ++mt) {
        #pragma unroll
        for (int j = 0; j < 4; ++j) {
            #pragma unroll
            for (int h = 0; h < 2; ++h) {
                const int mrow = rowBase + wm * 32 + mt * 16 + r;
                const int ncol = wn * 64 + j * 16 + h * 8 + cpair;
                float* c0 = Cg + (size_t)mrow * Nc + ncol;
                float* c1 = Cg + (size_t)(mrow + 8) * Nc + ncol;
                *(float2*)c0 = make_float2(acc[mt][j][h][0], acc[mt][j][h][1]);
                *(float2*)c1 = make_float2(acc[mt][j][h][2], acc[mt][j][h][3]);
            }
        }
    }
}

// ── Launch ──────────────────────────────────────────────────────────
extern "C" void kernel_launch(void* const* d_in, const int* in_sizes, int n_in,
                              void* d_out, int out_size)
{
    const float* a    = (const float*)d_in[0];   // [B,H,M,K] fp32
    const int*   mask = (const int*)d_in[1];     // [B,1,M,K] int32
    const float* b    = (const float*)d_in[2];   // [B,H,K,N] fp32
    float*       out  = (float*)d_out;           // [B,H,M,N] fp32

    cudaFuncSetAttribute(masked_gemm_hmma,
                         cudaFuncAttributeMaxDynamicSharedMemorySize, SMEM_BYTES);

    dim3 grid(Mc / BM, Bc * Hc);                 // (16, 32) = 512 CTAs
    masked_gemm_hmma<<<grid, NTH, SMEM_BYTES>>>(a, mask, b, out);
}